// round 1
// baseline (speedup 1.0000x reference)
#include <cuda_runtime.h>
#include <math.h>

#define IMG_H 1088
#define IMG_W 1920
#define BATCH 8
#define TILE  32
#define NT    256

// Fused Canny pipeline. One CTA computes a 32x32 output tile for all 5 planes.
// Stencil chain halos: edges<-thin(1)<-mag(1)<-blur(1)<-img(3) => img halo 6.
__global__ __launch_bounds__(NT) void canny_kernel(
    const float* __restrict__ img,
    const float* __restrict__ gk,    // 7x7 gaussian (separable by construction)
    const float* __restrict__ sh,    // 3x3 sobel horizontal
    const float* __restrict__ sv,    // 3x3 sobel vertical
    float* __restrict__ out,
    long long N)
{
    __shared__ float s_img [44][45];  // img tile, origin (by-6, bx-6)
    __shared__ float s_tmp [44][39];  // row-convolved, origin (by-6, bx-3)
    __shared__ float s_blur[38][39];  // blurred, origin (by-3, bx-3), 0 outside image
    __shared__ float s_mag [36][37];  // grad mag, origin (by-2, bx-2), 0 outside image
    __shared__ float s_thin[34][35];  // thin edges, origin (by-1, bx-1), 0 outside image
    __shared__ float s_r[7], s_c[7], s_sh[9], s_sv[9];

    const int tid = threadIdx.x;
    const int bx = blockIdx.x * TILE;
    const int by = blockIdx.y * TILE;
    const int b  = blockIdx.z;
    const float* ip = img + (long long)b * IMG_H * IMG_W;

    if (tid < 9) { s_sh[tid] = sh[tid]; s_sv[tid] = sv[tid]; }
    if (tid < 7) {
        // gaussian is a normalized outer product: k[i][j] = k[i][4]*k[4][j]/k[4][4]
        float s = sqrtf(gk[4 * 7 + 4]);
        s_r[tid] = gk[tid * 7 + 4] / s;   // column (vertical) factor
        s_c[tid] = gk[4 * 7 + tid] / s;   // row (horizontal) factor
    }

    // ---- stage 0: load img tile (44x44) with zero padding ----
    #pragma unroll
    for (int idx = tid; idx < 44 * 44; idx += NT) {
        int ly = idx / 44, lx = idx % 44;
        int gy = by - 6 + ly, gx = bx - 6 + lx;
        float v = 0.0f;
        if (gy >= 0 && gy < IMG_H && gx >= 0 && gx < IMG_W)
            v = ip[(long long)gy * IMG_W + gx];
        s_img[ly][lx] = v;
    }
    __syncthreads();

    // ---- stage 1a: horizontal 7-tap (44 rows x 38 cols) ----
    {
        float c0 = s_c[0], c1 = s_c[1], c2 = s_c[2], c3 = s_c[3],
              c4 = s_c[4], c5 = s_c[5], c6 = s_c[6];
        for (int idx = tid; idx < 44 * 38; idx += NT) {
            int ly = idx / 38, lx = idx % 38;
            const float* p = &s_img[ly][lx];
            s_tmp[ly][lx] = c0 * p[0] + c1 * p[1] + c2 * p[2] + c3 * p[3]
                          + c4 * p[4] + c5 * p[5] + c6 * p[6];
        }
    }
    __syncthreads();

    // ---- stage 1b: vertical 7-tap -> blurred (38x38), zeroed outside image ----
    {
        float r0 = s_r[0], r1 = s_r[1], r2 = s_r[2], r3 = s_r[3],
              r4 = s_r[4], r5 = s_r[5], r6 = s_r[6];
        for (int idx = tid; idx < 38 * 38; idx += NT) {
            int ly = idx / 38, lx = idx % 38;
            int gy = by - 3 + ly, gx = bx - 3 + lx;
            float v = 0.0f;
            if (gy >= 0 && gy < IMG_H && gx >= 0 && gx < IMG_W)
                v = r0 * s_tmp[ly + 0][lx] + r1 * s_tmp[ly + 1][lx]
                  + r2 * s_tmp[ly + 2][lx] + r3 * s_tmp[ly + 3][lx]
                  + r4 * s_tmp[ly + 4][lx] + r5 * s_tmp[ly + 5][lx]
                  + r6 * s_tmp[ly + 6][lx];
            s_blur[ly][lx] = v;
        }
    }
    __syncthreads();

    // ---- stage 2: sobel -> grad magnitude (36x36), zeroed outside image ----
    {
        float h0 = s_sh[0], h1 = s_sh[1], h2 = s_sh[2], h3 = s_sh[3], h4 = s_sh[4],
              h5 = s_sh[5], h6 = s_sh[6], h7 = s_sh[7], h8 = s_sh[8];
        float v0 = s_sv[0], v1 = s_sv[1], v2 = s_sv[2], v3 = s_sv[3], v4 = s_sv[4],
              v5 = s_sv[5], v6 = s_sv[6], v7 = s_sv[7], v8 = s_sv[8];
        for (int idx = tid; idx < 36 * 36; idx += NT) {
            int ly = idx / 36, lx = idx % 36;
            int gy = by - 2 + ly, gx = bx - 2 + lx;
            float v = 0.0f;
            if (gy >= 0 && gy < IMG_H && gx >= 0 && gx < IMG_W) {
                float b00 = s_blur[ly][lx],     b01 = s_blur[ly][lx + 1],     b02 = s_blur[ly][lx + 2];
                float b10 = s_blur[ly + 1][lx], b11 = s_blur[ly + 1][lx + 1], b12 = s_blur[ly + 1][lx + 2];
                float b20 = s_blur[ly + 2][lx], b21 = s_blur[ly + 2][lx + 1], b22 = s_blur[ly + 2][lx + 2];
                float gxv = h0*b00 + h1*b01 + h2*b02 + h3*b10 + h4*b11 + h5*b12 + h6*b20 + h7*b21 + h8*b22;
                float gyv = v0*b00 + v1*b01 + v2*b02 + v3*b10 + v4*b11 + v5*b12 + v6*b20 + v7*b21 + v8*b22;
                v = sqrtf(gxv * gxv + gyv * gyv);
            }
            s_mag[ly][lx] = v;
        }
    }
    __syncthreads();

    // ---- stage 3: non-max suppression -> thin edges (34x34), zeroed outside ----
    for (int idx = tid; idx < 34 * 34; idx += NT) {
        int ly = idx / 34, lx = idx % 34;
        int gy = by - 1 + ly, gx = bx - 1 + lx;
        float v = 0.0f;
        if (gy >= 0 && gy < IMG_H && gx >= 0 && gx < IMG_W) {
            float m00 = s_mag[ly][lx],     m01 = s_mag[ly][lx + 1],     m02 = s_mag[ly][lx + 2];
            float m10 = s_mag[ly + 1][lx],                              m12 = s_mag[ly + 1][lx + 2];
            float m20 = s_mag[ly + 2][lx], m21 = s_mag[ly + 2][lx + 1], m22 = s_mag[ly + 2][lx + 2];
            float m   = s_mag[ly + 1][lx + 1];
            // max_k = [[1,0,-1],[2,0,-2],[1,0,-1]]; sx = corr(mag, max_k), sy = corr(mag, max_k^T)
            float sx = m00 - m02 + 2.0f * m10 - 2.0f * m12 + m20 - m22;
            float sy = m00 + 2.0f * m01 + m02 - m20 - 2.0f * m21 - m22;
            v = (m >= sx && m >= sy) ? m : 0.0f;
        }
        s_thin[ly][lx] = v;
    }
    __syncthreads();

    // ---- stage 4: hysteresis + all 5 plane writes (32x32) ----
    {
        float h0 = s_sh[0], h1 = s_sh[1], h2 = s_sh[2], h3 = s_sh[3], h4 = s_sh[4],
              h5 = s_sh[5], h6 = s_sh[6], h7 = s_sh[7], h8 = s_sh[8];
        float v0 = s_sv[0], v1 = s_sv[1], v2 = s_sv[2], v3 = s_sv[3], v4 = s_sv[4],
              v5 = s_sv[5], v6 = s_sv[6], v7 = s_sv[7], v8 = s_sv[8];
        #pragma unroll
        for (int idx = tid; idx < TILE * TILE; idx += NT) {
            int ly = idx / TILE, lx = idx % TILE;
            int gy = by + ly, gx = bx + lx;
            long long o = (long long)b * IMG_H * IMG_W + (long long)gy * IMG_W + gx;

            float blur = s_blur[ly + 3][lx + 3];
            float m    = s_mag [ly + 2][lx + 2];

            // orientation from gx/gy at the tile point (blur origin offset +3, window +-1)
            float b00 = s_blur[ly + 2][lx + 2], b01 = s_blur[ly + 2][lx + 3], b02 = s_blur[ly + 2][lx + 4];
            float b10 = s_blur[ly + 3][lx + 2], b11 = s_blur[ly + 3][lx + 3], b12 = s_blur[ly + 3][lx + 4];
            float b20 = s_blur[ly + 4][lx + 2], b21 = s_blur[ly + 4][lx + 3], b22 = s_blur[ly + 4][lx + 4];
            float gxv = h0*b00 + h1*b01 + h2*b02 + h3*b10 + h4*b11 + h5*b12 + h6*b20 + h7*b21 + h8*b22;
            float gyv = v0*b00 + v1*b01 + v2*b02 + v3*b10 + v4*b11 + v5*b12 + v6*b20 + v7*b21 + v8*b22;
            float orient = atan2f(gyv, gxv);

            float t = s_thin[ly + 1][lx + 1];
            bool strong = t > 3.0f;
            bool weak   = (t > 1.0f) && (t <= 3.0f);
            int nsum =
                (s_thin[ly][lx]     > 3.0f) + (s_thin[ly][lx + 1]     > 3.0f) + (s_thin[ly][lx + 2]     > 3.0f) +
                (s_thin[ly + 1][lx] > 3.0f) +                                   (s_thin[ly + 1][lx + 2] > 3.0f) +
                (s_thin[ly + 2][lx] > 3.0f) + (s_thin[ly + 2][lx + 1] > 3.0f) + (s_thin[ly + 2][lx + 2] > 3.0f);
            // hyst_k center = -8: conv = nsum - 8*strong_center; strong_neighbors = conv > 0
            bool sn   = (nsum - 8 * (strong ? 1 : 0)) > 0;
            bool edge = strong || (weak && sn);

            out[o]         = blur;
            out[N + o]     = m;
            out[2 * N + o] = orient;
            out[3 * N + o] = t;
            out[4 * N + o] = edge ? 1.0f : 0.0f;
        }
    }
}

extern "C" void kernel_launch(void* const* d_in, const int* in_sizes, int n_in,
                              void* d_out, int out_size) {
    const float* img = (const float*)d_in[0];
    const float* gk  = (const float*)d_in[1];
    const float* sh  = (const float*)d_in[2];
    const float* sv  = (const float*)d_in[3];
    float* out = (float*)d_out;
    long long N = (long long)out_size / 5;   // 5 concatenated planes
    dim3 grid(IMG_W / TILE, IMG_H / TILE, BATCH);
    canny_kernel<<<grid, NT>>>(img, gk, sh, sv, out, N);
}